// round 1
// baseline (speedup 1.0000x reference)
#include <cuda_runtime.h>
#include <math.h>

#define B_  64
#define T_  1024
#define J_  128
#define D_  256
#define TILE_T 32      // rows of t per CTA
#define ROWS   4       // rows per warp
#define THREADS 256
#define USTRIDE 129    // odd stride -> conflict-free for both access patterns

// smem floats: U[256][129] + su[128] + hrow[32][256]
#define SMEM_FLOATS (D_*USTRIDE + J_ + TILE_T*D_)
#define SMEM_BYTES  (SMEM_FLOATS * 4)

// scratch (no allocations allowed)
__device__ float g_L[B_*T_];                    // L[b,t] = sh + max_j(dot+su)
__device__ __align__(16) float g_Q2C[B_*D_];    // Q2C[b,d]

// ---------------------------------------------------------------------------
// K1: per (t-tile, b): S logits, softmax over j, C2Q, G chunks 0..2, L.
// ---------------------------------------------------------------------------
__global__ void __launch_bounds__(THREADS, 1)
bidaf_main(const float* __restrict__ H, const float* __restrict__ U,
           const float* __restrict__ w_h, const float* __restrict__ w_u,
           const float* __restrict__ w_hu, float* __restrict__ G)
{
    extern __shared__ float sm[];
    float* Usm  = sm;                          // [256][129], Usm[d][j]
    float* suS  = Usm + D_*USTRIDE;            // [128]
    float* hrow = suS + J_;                    // [32][256], per-warp rows (reused for A)

    const int b    = blockIdx.y;
    const int lane = threadIdx.x & 31;
    const int warp = threadIdx.x >> 5;

    float wh[8], wu[8], whu[8];
#pragma unroll
    for (int c = 0; c < 8; c++) {
        int d = lane + 32*c;
        wh[c] = w_h[d]; wu[c] = w_u[d]; whu[c] = w_hu[d];
    }

    // --- load U[b] transposed into smem: Usm[d][j] ---
    const float4* U4 = (const float4*)(U + (size_t)b * J_ * D_);
    for (int k = threadIdx.x; k < J_*(D_/4); k += THREADS) {
        int j = k >> 6, c4 = k & 63;
        float4 v = U4[k];
        Usm[(c4*4+0)*USTRIDE + j] = v.x;
        Usm[(c4*4+1)*USTRIDE + j] = v.y;
        Usm[(c4*4+2)*USTRIDE + j] = v.z;
        Usm[(c4*4+3)*USTRIDE + j] = v.w;
    }

    // --- su[j] = dot(U[b,j], w_u); warp w handles j = w*16 .. w*16+15 ---
    const float* Ub = U + (size_t)b * J_ * D_;
    for (int jj = 0; jj < 16; jj++) {
        int j = warp*16 + jj;
        const float* Uj = Ub + (size_t)j * D_;
        float s = 0.f;
#pragma unroll
        for (int c = 0; c < 8; c++) s += Uj[lane + 32*c] * wu[c];
#pragma unroll
        for (int o = 16; o; o >>= 1) s += __shfl_xor_sync(0xffffffffu, s, o);
        if (lane == 0) suS[j] = s;
    }
    __syncthreads();

    const int tBase = blockIdx.x * TILE_T + warp * ROWS;
    float* hb = hrow + warp * ROWS * D_;

    // --- load ROWS rows of H: compute sh, stash H*w_hu in smem ---
    float sh[ROWS];
#pragma unroll
    for (int r = 0; r < ROWS; r++) {
        const float* Hr = H + ((size_t)(b*T_ + tBase + r)) * D_;
        float s = 0.f;
#pragma unroll
        for (int c = 0; c < 8; c++) {
            float x = Hr[lane + 32*c];
            s += x * wh[c];
            hb[r*D_ + lane + 32*c] = x * whu[c];
        }
#pragma unroll
        for (int o = 16; o; o >>= 1) s += __shfl_xor_sync(0xffffffffu, s, o);
        sh[r] = s;
    }
    __syncwarp();

    // --- S logits: acc[r][q], j = lane + 32*q ---
    float acc[ROWS][4];
#pragma unroll
    for (int r = 0; r < ROWS; r++)
#pragma unroll
        for (int q = 0; q < 4; q++) acc[r][q] = 0.f;

#pragma unroll 8
    for (int d = 0; d < D_; d++) {
        float u0 = Usm[d*USTRIDE + lane];
        float u1 = Usm[d*USTRIDE + lane + 32];
        float u2 = Usm[d*USTRIDE + lane + 64];
        float u3 = Usm[d*USTRIDE + lane + 96];
        float h0 = hb[d], h1 = hb[D_ + d], h2 = hb[2*D_ + d], h3 = hb[3*D_ + d];
        acc[0][0] += h0*u0; acc[0][1] += h0*u1; acc[0][2] += h0*u2; acc[0][3] += h0*u3;
        acc[1][0] += h1*u0; acc[1][1] += h1*u1; acc[1][2] += h1*u2; acc[1][3] += h1*u3;
        acc[2][0] += h2*u0; acc[2][1] += h2*u1; acc[2][2] += h2*u2; acc[2][3] += h2*u3;
        acc[3][0] += h3*u0; acc[3][1] += h3*u1; acc[3][2] += h3*u2; acc[3][3] += h3*u3;
    }

    // --- +su, softmax over j (sh cancels), emit L = sh + max ---
#pragma unroll
    for (int r = 0; r < ROWS; r++) {
        float m = -1e30f;
#pragma unroll
        for (int q = 0; q < 4; q++) {
            acc[r][q] += suS[lane + 32*q];
            m = fmaxf(m, acc[r][q]);
        }
#pragma unroll
        for (int o = 16; o; o >>= 1) m = fmaxf(m, __shfl_xor_sync(0xffffffffu, m, o));
        float s = 0.f;
#pragma unroll
        for (int q = 0; q < 4; q++) {
            float e = expf(acc[r][q] - m);
            acc[r][q] = e; s += e;
        }
#pragma unroll
        for (int o = 16; o; o >>= 1) s += __shfl_xor_sync(0xffffffffu, s, o);
        float inv = 1.0f / s;
#pragma unroll
        for (int q = 0; q < 4; q++) acc[r][q] *= inv;
        if (lane == 0) g_L[b*T_ + tBase + r] = sh[r] + m;
    }
    __syncwarp();

    // stash A rows in hb (h-scaled values no longer needed)
#pragma unroll
    for (int r = 0; r < ROWS; r++)
#pragma unroll
        for (int q = 0; q < 4; q++)
            hb[r*D_ + lane + 32*q] = acc[r][q];
    __syncwarp();

    // --- C2Q[r][d], d = lane + 32*c ---
    float cacc[ROWS][8];
#pragma unroll
    for (int r = 0; r < ROWS; r++)
#pragma unroll
        for (int c = 0; c < 8; c++) cacc[r][c] = 0.f;

#pragma unroll 2
    for (int j = 0; j < J_; j++) {
        float a0 = hb[j], a1 = hb[D_ + j], a2 = hb[2*D_ + j], a3 = hb[3*D_ + j];
#pragma unroll
        for (int c = 0; c < 8; c++) {
            float u = Usm[(lane + 32*c)*USTRIDE + j];
            cacc[0][c] += a0*u; cacc[1][c] += a1*u;
            cacc[2][c] += a2*u; cacc[3][c] += a3*u;
        }
    }

    // --- epilogue: G chunks [H, C2Q, H*C2Q] ---
#pragma unroll
    for (int r = 0; r < ROWS; r++) {
        const float* Hr = H + ((size_t)(b*T_ + tBase + r)) * D_;
        float* Gr = G + ((size_t)(b*T_ + tBase + r)) * (4*D_);
#pragma unroll
        for (int c = 0; c < 8; c++) {
            int d = lane + 32*c;
            float h  = Hr[d];
            float cq = cacc[r][c];
            Gr[d]        = h;
            Gr[D_ + d]   = cq;
            Gr[2*D_ + d] = h * cq;
        }
    }
}

// ---------------------------------------------------------------------------
// K2: per batch: softmax over t of L, Q2C[b,d] = sum_t w[t]*H[b,t,d]
// ---------------------------------------------------------------------------
__global__ void __launch_bounds__(1024)
bidaf_q2c(const float* __restrict__ H)
{
    const int b = blockIdx.x, tid = threadIdx.x;
    __shared__ float wsm[T_];
    __shared__ float red[32];
    __shared__ float qpart[4][D_];

    const int lane = tid & 31, wid = tid >> 5;
    float l = g_L[b*T_ + tid];

    float m = l;
#pragma unroll
    for (int o = 16; o; o >>= 1) m = fmaxf(m, __shfl_xor_sync(0xffffffffu, m, o));
    if (lane == 0) red[wid] = m;
    __syncthreads();
    if (wid == 0) {
        float v = red[lane];
#pragma unroll
        for (int o = 16; o; o >>= 1) v = fmaxf(v, __shfl_xor_sync(0xffffffffu, v, o));
        if (lane == 0) red[0] = v;
    }
    __syncthreads();
    m = red[0];
    float e = expf(l - m);
    float s = e;
#pragma unroll
    for (int o = 16; o; o >>= 1) s += __shfl_xor_sync(0xffffffffu, s, o);
    __syncthreads();                 // everyone read red[0] before rewrite
    if (lane == 0) red[wid] = s;
    __syncthreads();
    if (wid == 0) {
        float v = red[lane];
#pragma unroll
        for (int o = 16; o; o >>= 1) v += __shfl_xor_sync(0xffffffffu, v, o);
        if (lane == 0) red[0] = v;
    }
    __syncthreads();
    wsm[tid] = e / red[0];
    __syncthreads();

    const int d = tid & (D_-1), seg = tid >> 8;    // 4 segs of 256 t
    const float* Hp = H + (size_t)b*T_*D_ + (size_t)(seg*256)*D_ + d;
    float acc = 0.f;
#pragma unroll 4
    for (int tt = 0; tt < 256; tt++)
        acc += wsm[seg*256 + tt] * Hp[(size_t)tt * D_];
    qpart[seg][d] = acc;
    __syncthreads();
    if (tid < D_)
        g_Q2C[b*D_ + tid] = qpart[0][tid] + qpart[1][tid] + qpart[2][tid] + qpart[3][tid];
}

// ---------------------------------------------------------------------------
// K3: G chunk 3 = H * Q2C (broadcast over t), float4
// ---------------------------------------------------------------------------
__global__ void __launch_bounds__(256)
bidaf_g3(const float* __restrict__ H, float* __restrict__ G)
{
    int idx = blockIdx.x * 256 + threadIdx.x;      // 0 .. B*T*D/4-1
    int d4 = idx & 63;
    int t  = (idx >> 6) & (T_-1);
    int b  = idx >> 16;
    float4 h = ((const float4*)H)[idx];
    float4 q = ((const float4*)g_Q2C)[b*(D_/4) + d4];
    float4 o = make_float4(h.x*q.x, h.y*q.y, h.z*q.z, h.w*q.w);
    ((float4*)G)[((size_t)(b*T_ + t))*(4*D_/4) + 3*(D_/4) + d4] = o;
}

// ---------------------------------------------------------------------------
extern "C" void kernel_launch(void* const* d_in, const int* in_sizes, int n_in,
                              void* d_out, int out_size)
{
    const float* H   = (const float*)d_in[0];
    const float* U   = (const float*)d_in[1];
    const float* wh  = (const float*)d_in[2];
    const float* wu  = (const float*)d_in[3];
    const float* whu = (const float*)d_in[4];
    float* G = (float*)d_out;

    cudaFuncSetAttribute(bidaf_main, cudaFuncAttributeMaxDynamicSharedMemorySize, SMEM_BYTES);

    dim3 g1(T_/TILE_T, B_);
    bidaf_main<<<g1, THREADS, SMEM_BYTES>>>(H, U, wh, wu, whu, G);
    bidaf_q2c<<<B_, 1024>>>(H);
    bidaf_g3<<<(B_*T_*D_/4)/256, 256>>>(H, G);
}

// round 2
// speedup vs baseline: 1.2620x; 1.2620x over previous
#include <cuda_runtime.h>
#include <math.h>

#define B_  64
#define T_  1024
#define J_  128
#define D_  256
#define TILE_T 64
#define THREADS 512
#define NW 16
#define HRS 66     // Hsm row stride (even -> 8B-aligned float2 rows; 4*66 mod 32 = 8 -> bounded STS conflicts)

// smem layout (floats)
#define OFF_U   0                      // U[j][d] natural layout: 128*256 = 32768
#define OFF_H   (J_*D_)                // Hsm[d][row] scaled by w_hu: 256*66 = 16896
#define OFF_A   OFF_H                  // Asm[j][row] 128*64 aliases Hsm after GEMM1
#define OFF_SU  (OFF_H + D_*HRS)       // su[j]: 128
#define OFF_SH  (OFF_SU + J_)          // sh half-partials [row][2]: 128
#define OFF_RM  (OFF_SH + 128)         // max partials [NW][64]: 1024
#define OFF_RS  (OFF_RM + NW*TILE_T)   // sum partials [NW][64]: 1024
#define SMEM_FLOATS (OFF_RS + NW*TILE_T)
#define SMEM_BYTES  (SMEM_FLOATS * 4)  // 207872 B

__device__ float g_L[B_*T_];
__device__ __align__(16) float g_Q2C[B_*D_];

__device__ __forceinline__ float4 fma4(float a, float4 u, float4 c) {
    c.x = fmaf(a, u.x, c.x); c.y = fmaf(a, u.y, c.y);
    c.z = fmaf(a, u.z, c.z); c.w = fmaf(a, u.w, c.w);
    return c;
}

// ---------------------------------------------------------------------------
// K1: per (t-tile 64, b): S logits, softmax over j, C2Q, G chunks 0..2, L.
// ---------------------------------------------------------------------------
__global__ void __launch_bounds__(THREADS, 1)
bidaf_main(const float* __restrict__ H, const float* __restrict__ U,
           const float* __restrict__ w_h, const float* __restrict__ w_u,
           const float* __restrict__ w_hu, float* __restrict__ G)
{
    extern __shared__ float sm[];
    float* Usm  = sm + OFF_U;
    float* Hsm  = sm + OFF_H;
    float* Asm  = sm + OFF_A;
    float* suS  = sm + OFF_SU;
    float* shS  = sm + OFF_SH;
    float* redM = sm + OFF_RM;
    float* redS = sm + OFF_RS;

    const int tid  = threadIdx.x;
    const int lane = tid & 31;
    const int warp = tid >> 5;
    const int b    = blockIdx.y;
    const int tb   = blockIdx.x * TILE_T;

    // --- stage U[b] straight copy (natural [j][d] layout, coalesced) ---
    {
        const float4* U4 = (const float4*)(U + (size_t)b * J_ * D_);
        float4* Us4 = (float4*)Usm;
#pragma unroll
        for (int it = 0; it < (J_*D_/4)/THREADS; it++)
            Us4[tid + it*THREADS] = U4[tid + it*THREADS];
    }
    // --- stage H tile scaled by w_hu, transposed -> Hsm[d][row]; sh half-partials ---
    {
        const float4* wh4  = (const float4*)w_h;
        const float4* whu4 = (const float4*)w_hu;
#pragma unroll
        for (int it = 0; it < (TILE_T*D_/4)/THREADS; it++) {
            int k = tid + it*THREADS;
            int row = k >> 6, d4 = k & 63;       // within a warp: row constant, d4 spans a 32-half
            float4 hv = ((const float4*)(H + ((size_t)(b*T_ + tb + row)) * D_))[d4];
            float4 wv = whu4[d4];
            float4 av = wh4[d4];
            float ph = hv.x*av.x + hv.y*av.y + hv.z*av.z + hv.w*av.w;
#pragma unroll
            for (int o = 16; o; o >>= 1) ph += __shfl_xor_sync(0xffffffffu, ph, o);
            Hsm[(4*d4+0)*HRS + row] = hv.x * wv.x;
            Hsm[(4*d4+1)*HRS + row] = hv.y * wv.y;
            Hsm[(4*d4+2)*HRS + row] = hv.z * wv.z;
            Hsm[(4*d4+3)*HRS + row] = hv.w * wv.w;
            if (lane == 0) shS[row*2 + (warp & 1)] = ph;
        }
    }
    __syncthreads();

    // --- su[j] = dot(U[j], w_u); warp handles 8 j ---
    {
        float wu[8];
#pragma unroll
        for (int c = 0; c < 8; c++) wu[c] = w_u[lane + 32*c];
#pragma unroll
        for (int jj = 0; jj < J_/NW; jj++) {
            int j = warp*(J_/NW) + jj;
            const float* Uj = Usm + j*D_;
            float s = 0.f;
#pragma unroll
            for (int c = 0; c < 8; c++) s = fmaf(Uj[lane + 32*c], wu[c], s);
#pragma unroll
            for (int o = 16; o; o >>= 1) s += __shfl_xor_sync(0xffffffffu, s, o);
            if (lane == 0) suS[j] = s;
        }
    }

    // --- GEMM1: S[row][j] — rows wide over lanes (lane*2+rr), 8 j per warp ---
    const int rowA = lane * 2;
    const int jb   = warp * 8;
    float acc[2][8];
#pragma unroll
    for (int rr = 0; rr < 2; rr++)
#pragma unroll
        for (int jj = 0; jj < 8; jj++) acc[rr][jj] = 0.f;

    {
        const float* hp  = Hsm + rowA;
        const float* up0 = Usm + jb * D_;
#pragma unroll 2
        for (int d0 = 0; d0 < D_; d0 += 4) {
            float2 h0 = *(const float2*)(hp + (d0+0)*HRS);
            float2 h1 = *(const float2*)(hp + (d0+1)*HRS);
            float2 h2 = *(const float2*)(hp + (d0+2)*HRS);
            float2 h3 = *(const float2*)(hp + (d0+3)*HRS);
#pragma unroll
            for (int jj = 0; jj < 8; jj++) {
                float4 u = *(const float4*)(up0 + jj*D_ + d0);   // uniform addr -> broadcast
                acc[0][jj] = fmaf(h0.x,u.x, fmaf(h1.x,u.y, fmaf(h2.x,u.z, fmaf(h3.x,u.w, acc[0][jj]))));
                acc[1][jj] = fmaf(h0.y,u.x, fmaf(h1.y,u.y, fmaf(h2.y,u.z, fmaf(h3.y,u.w, acc[1][jj]))));
            }
        }
    }

    // --- softmax over j (cross-warp via smem partials); sh cancels, L = sh + max ---
    float su4[8];
#pragma unroll
    for (int q = 0; q < 2; q++) {
        float4 s4 = *(const float4*)(suS + jb + q*4);
        su4[q*4+0] = s4.x; su4[q*4+1] = s4.y; su4[q*4+2] = s4.z; su4[q*4+3] = s4.w;
    }
    float mloc[2] = {-1e30f, -1e30f};
#pragma unroll
    for (int rr = 0; rr < 2; rr++)
#pragma unroll
        for (int jj = 0; jj < 8; jj++) {
            acc[rr][jj] += su4[jj];
            mloc[rr] = fmaxf(mloc[rr], acc[rr][jj]);
        }
    redM[warp*TILE_T + rowA]     = mloc[0];
    redM[warp*TILE_T + rowA + 1] = mloc[1];
    __syncthreads();

    float mf[2];
#pragma unroll
    for (int rr = 0; rr < 2; rr++) {
        float m = redM[rowA + rr];
#pragma unroll
        for (int w = 1; w < NW; w++) m = fmaxf(m, redM[w*TILE_T + rowA + rr]);
        mf[rr] = m;
    }
    float sloc[2] = {0.f, 0.f};
#pragma unroll
    for (int rr = 0; rr < 2; rr++)
#pragma unroll
        for (int jj = 0; jj < 8; jj++) {
            float e = __expf(acc[rr][jj] - mf[rr]);
            acc[rr][jj] = e;
            sloc[rr] += e;
        }
    redS[warp*TILE_T + rowA]     = sloc[0];
    redS[warp*TILE_T + rowA + 1] = sloc[1];
    __syncthreads();

#pragma unroll
    for (int rr = 0; rr < 2; rr++) {
        float s = redS[rowA + rr];
#pragma unroll
        for (int w = 1; w < NW; w++) s += redS[w*TILE_T + rowA + rr];
        float inv = 1.0f / s;
#pragma unroll
        for (int jj = 0; jj < 8; jj++) acc[rr][jj] *= inv;
        if (warp == 0)
            g_L[b*T_ + tb + rowA + rr] =
                shS[(rowA+rr)*2] + shS[(rowA+rr)*2 + 1] + mf[rr];
    }
    // write A transposed into Asm[j][row] (overwrites Hsm — GEMM1 done by all, 2 barriers passed)
#pragma unroll
    for (int jj = 0; jj < 8; jj++) {
        Asm[(jb+jj)*TILE_T + rowA]     = acc[0][jj];
        Asm[(jb+jj)*TILE_T + rowA + 1] = acc[1][jj];
    }
    __syncthreads();

    // --- GEMM2: C2Q[row][d] — d wide over lanes (float4), warp = (row-group, d-half) ---
    const int rg   = warp >> 1;            // 8 row-groups of 8 rows
    const int dh   = warp & 1;             // 2 d-halves of 128
    const int dcol = dh*128 + lane*4;
    float4 c[8];
#pragma unroll
    for (int r = 0; r < 8; r++) c[r] = make_float4(0.f, 0.f, 0.f, 0.f);
    {
        const float* up = Usm + dcol;
        const float* ap = Asm + rg*8;
#pragma unroll 2
        for (int j = 0; j < J_; j++) {
            float4 u  = *(const float4*)(up);
            float4 a0 = *(const float4*)(ap);       // rows 0..3 broadcast
            float4 a1 = *(const float4*)(ap + 4);   // rows 4..7
            up += D_; ap += TILE_T;
            c[0] = fma4(a0.x, u, c[0]);
            c[1] = fma4(a0.y, u, c[1]);
            c[2] = fma4(a0.z, u, c[2]);
            c[3] = fma4(a0.w, u, c[3]);
            c[4] = fma4(a1.x, u, c[4]);
            c[5] = fma4(a1.y, u, c[5]);
            c[6] = fma4(a1.z, u, c[6]);
            c[7] = fma4(a1.w, u, c[7]);
        }
    }
    // --- epilogue: G chunks [H, C2Q, H*C2Q], fully coalesced float4 ---
#pragma unroll
    for (int r = 0; r < 8; r++) {
        int row = rg*8 + r;
        const float* Hr = H + ((size_t)(b*T_ + tb + row))*D_ + dcol;
        float*       Gr = G + ((size_t)(b*T_ + tb + row))*(4*D_) + dcol;
        float4 hg = *(const float4*)Hr;
        float4 cv = c[r];
        *(float4*)(Gr)          = hg;
        *(float4*)(Gr + D_)     = cv;
        *(float4*)(Gr + 2*D_)   = make_float4(hg.x*cv.x, hg.y*cv.y, hg.z*cv.z, hg.w*cv.w);
    }
}

// ---------------------------------------------------------------------------
// K2: per batch: softmax over t of L, Q2C[b,d] = sum_t w[t]*H[b,t,d]
// ---------------------------------------------------------------------------
__global__ void __launch_bounds__(1024)
bidaf_q2c(const float* __restrict__ H)
{
    const int b = blockIdx.x, tid = threadIdx.x;
    __shared__ float wsm[T_];
    __shared__ float red[32];
    __shared__ float qpart[4][D_];

    const int lane = tid & 31, wid = tid >> 5;
    float l = g_L[b*T_ + tid];

    float m = l;
#pragma unroll
    for (int o = 16; o; o >>= 1) m = fmaxf(m, __shfl_xor_sync(0xffffffffu, m, o));
    if (lane == 0) red[wid] = m;
    __syncthreads();
    if (wid == 0) {
        float v = red[lane];
#pragma unroll
        for (int o = 16; o; o >>= 1) v = fmaxf(v, __shfl_xor_sync(0xffffffffu, v, o));
        if (lane == 0) red[0] = v;
    }
    __syncthreads();
    m = red[0];
    float e = __expf(l - m);
    float s = e;
#pragma unroll
    for (int o = 16; o; o >>= 1) s += __shfl_xor_sync(0xffffffffu, s, o);
    __syncthreads();
    if (lane == 0) red[wid] = s;
    __syncthreads();
    if (wid == 0) {
        float v = red[lane];
#pragma unroll
        for (int o = 16; o; o >>= 1) v += __shfl_xor_sync(0xffffffffu, v, o);
        if (lane == 0) red[0] = v;
    }
    __syncthreads();
    wsm[tid] = e / red[0];
    __syncthreads();

    const int d = tid & (D_-1), seg = tid >> 8;
    const float* Hp = H + (size_t)b*T_*D_ + (size_t)(seg*256)*D_ + d;
    float acc = 0.f;
#pragma unroll 4
    for (int tt = 0; tt < 256; tt++)
        acc = fmaf(wsm[seg*256 + tt], Hp[(size_t)tt * D_], acc);
    qpart[seg][d] = acc;
    __syncthreads();
    if (tid < D_)
        g_Q2C[b*D_ + tid] = qpart[0][tid] + qpart[1][tid] + qpart[2][tid] + qpart[3][tid];
}

// ---------------------------------------------------------------------------
// K3: G chunk 3 = H * Q2C (broadcast over t), float4
// ---------------------------------------------------------------------------
__global__ void __launch_bounds__(256)
bidaf_g3(const float* __restrict__ H, float* __restrict__ G)
{
    int idx = blockIdx.x * 256 + threadIdx.x;
    int d4 = idx & 63;
    int t  = (idx >> 6) & (T_-1);
    int b  = idx >> 16;
    float4 h = ((const float4*)H)[idx];
    float4 q = ((const float4*)g_Q2C)[b*(D_/4) + d4];
    float4 o = make_float4(h.x*q.x, h.y*q.y, h.z*q.z, h.w*q.w);
    ((float4*)G)[((size_t)(b*T_ + t))*(4*D_/4) + 3*(D_/4) + d4] = o;
}

// ---------------------------------------------------------------------------
extern "C" void kernel_launch(void* const* d_in, const int* in_sizes, int n_in,
                              void* d_out, int out_size)
{
    const float* H   = (const float*)d_in[0];
    const float* U   = (const float*)d_in[1];
    const float* wh  = (const float*)d_in[2];
    const float* wu  = (const float*)d_in[3];
    const float* whu = (const float*)d_in[4];
    float* G = (float*)d_out;

    cudaFuncSetAttribute(bidaf_main, cudaFuncAttributeMaxDynamicSharedMemorySize, SMEM_BYTES);

    dim3 g1(T_/TILE_T, B_);
    bidaf_main<<<g1, THREADS, SMEM_BYTES>>>(H, U, wh, wu, whu, G);
    bidaf_q2c<<<B_, 1024>>>(H);
    bidaf_g3<<<(B_*T_*D_/4)/256, 256>>>(H, G);
}

// round 8
// speedup vs baseline: 2.2289x; 1.7662x over previous
#include <cuda_runtime.h>
#include <cuda_bf16.h>
#include <stdint.h>

#define B_  64
#define T_  1024
#define J_  128
#define D_  256
#define TT  128

// strides (bf16 elems / bytes)
#define USTB 528     // U row stride bytes (264 bf16): 132 words ≡ 4 mod 32 -> conflict-free ldmatrix
#define HSTB 272     // H/P row stride bytes (136 bf16): 68 words ≡ 4 mod 32

// smem byte offsets
#define SM_SH   0
#define SM_SU   512
#define SM_INV  1024
#define SM_RM   1536
#define SM_RS   3584
#define SM_PAD  5632
#define AU_HI   8192
#define AU_LO   (AU_HI + J_*USTB)       // +67584
#define AH_HI   (AU_LO + J_*USTB)
#define AH_LO   (AH_HI + TT*HSTB)       // +34816
#define SMEM_TOTAL (AH_LO + TT*HSTB)    // 213504 B
#define AP_HI   AH_HI                   // P overlays H after GEMM1
#define AP_LO   AH_LO

__device__ float g_L[B_*T_];
__device__ float g_Wt[B_*T_];
__device__ __align__(16) float g_Q2Cp[B_*8*D_];
__device__ __align__(16) float g_Q2C[B_*D_];

// ---------------- helpers ----------------
__device__ __forceinline__ uint32_t smem_u32(const void* p) {
    uint32_t a;
    asm("{ .reg .u64 t; cvta.to.shared.u64 t, %1; cvt.u32.u64 %0, t; }" : "=r"(a) : "l"(p));
    return a;
}
__device__ __forceinline__ void ldsm4(uint32_t* r, uint32_t addr) {
    asm volatile("ldmatrix.sync.aligned.m8n8.x4.shared.b16 {%0,%1,%2,%3}, [%4];"
        : "=r"(r[0]), "=r"(r[1]), "=r"(r[2]), "=r"(r[3]) : "r"(addr));
}
__device__ __forceinline__ void ldsm4t(uint32_t* r, uint32_t addr) {
    asm volatile("ldmatrix.sync.aligned.m8n8.x4.trans.shared.b16 {%0,%1,%2,%3}, [%4];"
        : "=r"(r[0]), "=r"(r[1]), "=r"(r[2]), "=r"(r[3]) : "r"(addr));
}
__device__ __forceinline__ void mma16816(float* c, const uint32_t* a, uint32_t b0, uint32_t b1) {
    asm volatile("mma.sync.aligned.m16n8k16.row.col.f32.bf16.bf16.f32 "
        "{%0,%1,%2,%3}, {%4,%5,%6,%7}, {%8,%9}, {%0,%1,%2,%3};"
        : "+f"(c[0]), "+f"(c[1]), "+f"(c[2]), "+f"(c[3])
        : "r"(a[0]), "r"(a[1]), "r"(a[2]), "r"(a[3]), "r"(b0), "r"(b1));
}
static __device__ __forceinline__ uint32_t pk(float a, float b) {
    return (uint32_t)__bfloat16_as_ushort(__float2bfloat16(a))
         | ((uint32_t)__bfloat16_as_ushort(__float2bfloat16(b)) << 16);
}
static __device__ __forceinline__ float rsd(float x) {
    return x - __bfloat162float(__float2bfloat16(x));
}

// ---------------------------------------------------------------------------
// K1: HMMA main kernel. 1 CTA per (b, 128-row t-tile). 8 warps.
// warp: rg = warp&3 -> 32 rows; jg/dg = warp>>2 -> 64-col group.
// ---------------------------------------------------------------------------
__global__ void __launch_bounds__(256, 1)
bidaf_main(const float* __restrict__ H, const float* __restrict__ U,
           const float* __restrict__ w_h, const float* __restrict__ w_u,
           const float* __restrict__ w_hu, float* __restrict__ G)
{
    extern __shared__ char smem[];
    const uint32_t sb = smem_u32(smem);
    float* shS  = (float*)(smem + SM_SH);
    float* suS  = (float*)(smem + SM_SU);
    float* invS = (float*)(smem + SM_INV);
    float* redM = (float*)(smem + SM_RM);
    float* redS = (float*)(smem + SM_RS);

    const int tid  = threadIdx.x;
    const int lane = tid & 31;
    const int warp = tid >> 5;
    const int rg   = warp & 3;
    const int jg   = warp >> 2;
    const int rbase = rg * 32;
    const int b    = blockIdx.y;
    const int tb   = blockIdx.x * TT;

    const int lr = lane & 7;
    const int g  = lane >> 3;
    // ldmatrix per-lane address components
    // A / P (row-major, stride HSTB): g&1 -> row+8, g>>1 -> k+8 (bytes +16)
    const uint32_t aoff = (uint32_t)((((g & 1) << 3) + lr) * HSTB + ((g >> 1) << 4));
    // B GEMM1 (U row-major [j][k], non-trans): g>>1 -> j+8, g&1 -> k+8
    const uint32_t boff = (uint32_t)((((g >> 1) << 3) + lr) * USTB + ((g & 1) << 4));
    // B GEMM2 (U via trans: rows j, cols d): g&1 -> j+8, g>>1 -> d+8
    const uint32_t toff = (uint32_t)((((g & 1) << 3) + lr) * USTB + ((g >> 1) << 4));

    // ---- stage U full-K (hi/lo) + su ----
    {
        const float4* wu4 = (const float4*)w_u;
        float4 wa = wu4[lane], wb = wu4[32 + lane];
#pragma unroll
        for (int it = 0; it < 16; it++) {
            int j = warp + it * 8;
            const float4* Uj = (const float4*)(U + (size_t)(b * J_ + j) * D_);
            float4 v0 = Uj[lane], v1 = Uj[32 + lane];
            float s = v0.x*wa.x + v0.y*wa.y + v0.z*wa.z + v0.w*wa.w
                    + v1.x*wb.x + v1.y*wb.y + v1.z*wb.z + v1.w*wb.w;
#pragma unroll
            for (int o = 16; o; o >>= 1) s += __shfl_xor_sync(0xffffffffu, s, o);
            if (lane == 0) suS[j] = s;
            uint32_t ro = (uint32_t)j * USTB + (uint32_t)lane * 8;
            *(uint2*)(smem + AU_HI + ro)       = make_uint2(pk(v0.x,v0.y), pk(v0.z,v0.w));
            *(uint2*)(smem + AU_HI + ro + 256) = make_uint2(pk(v1.x,v1.y), pk(v1.z,v1.w));
            *(uint2*)(smem + AU_LO + ro)       = make_uint2(pk(rsd(v0.x),rsd(v0.y)), pk(rsd(v0.z),rsd(v0.w)));
            *(uint2*)(smem + AU_LO + ro + 256) = make_uint2(pk(rsd(v1.x),rsd(v1.y)), pk(rsd(v1.z),rsd(v1.w)));
        }
    }

    float acc[2][8][4];
#pragma unroll
    for (int rt = 0; rt < 2; rt++)
#pragma unroll
        for (int nt = 0; nt < 8; nt++)
#pragma unroll
            for (int c = 0; c < 4; c++) acc[rt][nt][c] = 0.f;

    // ---- GEMM1 over two H k-chunks ----
    for (int kc = 0; kc < 2; kc++) {
        if (kc == 1) __syncthreads();   // chunk0 ldmatrix reads done before restage
        {   // stage H chunk (scaled by w_hu, hi/lo) + sh partial
            const float4* wh4  = (const float4*)w_h;
            const float4* whu4 = (const float4*)w_hu;
            float4 wv = wh4[kc*32 + lane];
            float4 mv = whu4[kc*32 + lane];
#pragma unroll
            for (int it = 0; it < 16; it++) {
                int row = warp + it * 8;
                float4 v = ((const float4*)(H + (size_t)(b*T_ + tb + row) * D_ + kc*128))[lane];
                float s = v.x*wv.x + v.y*wv.y + v.z*wv.z + v.w*wv.w;
#pragma unroll
                for (int o = 16; o; o >>= 1) s += __shfl_xor_sync(0xffffffffu, s, o);
                if (lane == 0) { if (kc == 0) shS[row] = s; else shS[row] += s; }
                float x0 = v.x*mv.x, x1 = v.y*mv.y, x2 = v.z*mv.z, x3 = v.w*mv.w;
                uint32_t ro = (uint32_t)row * HSTB + (uint32_t)lane * 8;
                *(uint2*)(smem + AH_HI + ro) = make_uint2(pk(x0,x1), pk(x2,x3));
                *(uint2*)(smem + AH_LO + ro) = make_uint2(pk(rsd(x0),rsd(x1)), pk(rsd(x2),rsd(x3)));
            }
        }
        __syncthreads();

        const uint32_t ahi = sb + AH_HI + aoff + (uint32_t)rbase * HSTB;
        const uint32_t alo = sb + AH_LO + aoff + (uint32_t)rbase * HSTB;
        const uint32_t bhiB = sb + AU_HI + boff + (uint32_t)(kc * 256);
        const uint32_t bloB = sb + AU_LO + boff + (uint32_t)(kc * 256);
#pragma unroll 2
        for (int ksl = 0; ksl < 8; ksl++) {
            uint32_t ak = (uint32_t)ksl * 32;
            uint32_t ah0[4], ah1[4], al0[4], al1[4];
            ldsm4(ah0, ahi + ak);
            ldsm4(ah1, ahi + ak + 16u*HSTB);
            ldsm4(al0, alo + ak);
            ldsm4(al1, alo + ak + 16u*HSTB);
#pragma unroll
            for (int nt2 = 0; nt2 < 4; nt2++) {
                uint32_t jb = (uint32_t)(jg*64 + nt2*16) * USTB + ak;
                uint32_t bh[4], bl[4];
                ldsm4(bh, bhiB + jb);
                mma16816(acc[0][2*nt2],   ah0, bh[0], bh[1]);
                mma16816(acc[0][2*nt2+1], ah0, bh[2], bh[3]);
                mma16816(acc[1][2*nt2],   ah1, bh[0], bh[1]);
                mma16816(acc[1][2*nt2+1], ah1, bh[2], bh[3]);
                mma16816(acc[0][2*nt2],   al0, bh[0], bh[1]);
                mma16816(acc[0][2*nt2+1], al0, bh[2], bh[3]);
                mma16816(acc[1][2*nt2],   al1, bh[0], bh[1]);
                mma16816(acc[1][2*nt2+1], al1, bh[2], bh[3]);
                ldsm4(bl, bloB + jb);
                mma16816(acc[0][2*nt2],   ah0, bl[0], bl[1]);
                mma16816(acc[0][2*nt2+1], ah0, bl[2], bl[3]);
                mma16816(acc[1][2*nt2],   ah1, bl[0], bl[1]);
                mma16816(acc[1][2*nt2+1], ah1, bl[2], bl[3]);
            }
        }
    }

    // ---- softmax over j (in-register on fragments, cross-warp via smem) ----
    // rows: r(rt,hf) = rbase + rt*16 + hf*8 + lane/4 ; cols: j = jg*64 + nt*8 + (lane&3)*2
    {
        const int q2 = (lane & 3) * 2;
        float su2[8][2];
#pragma unroll
        for (int nt = 0; nt < 8; nt++) {
            float2 s2 = *(const float2*)(suS + jg*64 + nt*8 + q2);
            su2[nt][0] = s2.x; su2[nt][1] = s2.y;
        }
        float mx[4];
#pragma unroll
        for (int rt = 0; rt < 2; rt++)
#pragma unroll
            for (int hf = 0; hf < 2; hf++) {
                float m = -1e30f;
#pragma unroll
                for (int nt = 0; nt < 8; nt++) {
                    float v0 = acc[rt][nt][2*hf]   + su2[nt][0];
                    float v1 = acc[rt][nt][2*hf+1] + su2[nt][1];
                    acc[rt][nt][2*hf] = v0; acc[rt][nt][2*hf+1] = v1;
                    m = fmaxf(m, fmaxf(v0, v1));
                }
                m = fmaxf(m, __shfl_xor_sync(0xffffffffu, m, 1));
                m = fmaxf(m, __shfl_xor_sync(0xffffffffu, m, 2));
                mx[2*rt+hf] = m;
            }
        const int rI = rbase + (lane >> 2);
        if ((lane & 3) == 0) {
#pragma unroll
            for (int rt = 0; rt < 2; rt++)
#pragma unroll
                for (int hf = 0; hf < 2; hf++)
                    redM[jg*128 + rI + rt*16 + hf*8] = mx[2*rt+hf];
        }
        __syncthreads();
        float mf[4], sm[4];
#pragma unroll
        for (int rt = 0; rt < 2; rt++)
#pragma unroll
            for (int hf = 0; hf < 2; hf++) {
                int r = rI + rt*16 + hf*8;
                float m = fmaxf(redM[r], redM[128 + r]);
                mf[2*rt+hf] = m;
                float s = 0.f;
#pragma unroll
                for (int nt = 0; nt < 8; nt++) {
                    float e0 = __expf(acc[rt][nt][2*hf]   - m);
                    float e1 = __expf(acc[rt][nt][2*hf+1] - m);
                    acc[rt][nt][2*hf] = e0; acc[rt][nt][2*hf+1] = e1;
                    s += e0 + e1;
                }
                s += __shfl_xor_sync(0xffffffffu, s, 1);
                s += __shfl_xor_sync(0xffffffffu, s, 2);
                sm[2*rt+hf] = s;
            }
        if ((lane & 3) == 0) {
#pragma unroll
            for (int k = 0; k < 4; k++)
                redS[jg*128 + rI + (k>>1)*16 + (k&1)*8] = sm[k];
        }
        __syncthreads();
        // write P (unnormalized e) hi/lo; inv + L once per row
#pragma unroll
        for (int rt = 0; rt < 2; rt++)
#pragma unroll
            for (int hf = 0; hf < 2; hf++) {
                int r = rI + rt*16 + hf*8;
                if (jg == 0 && (lane & 3) == 0) {
                    float tot = redS[r] + redS[128 + r];
                    invS[r] = 1.0f / tot;
                    g_L[b*T_ + tb + r] = shS[r] + mf[2*rt+hf];
                }
#pragma unroll
                for (int nt = 0; nt < 8; nt++) {
                    float e0 = acc[rt][nt][2*hf], e1 = acc[rt][nt][2*hf+1];
                    uint32_t o = (uint32_t)r * HSTB + (uint32_t)(jg*64 + nt*8 + q2) * 2;
                    *(uint32_t*)(smem + AP_HI + o) = pk(e0, e1);
                    *(uint32_t*)(smem + AP_LO + o) = pk(rsd(e0), rsd(e1));
                }
            }
    }
    __syncthreads();

    // ---- GEMM2 (two d-halves) + epilogue ----
    const uint32_t phi = sb + AP_HI + aoff + (uint32_t)rbase * HSTB;
    const uint32_t plo = sb + AP_LO + aoff + (uint32_t)rbase * HSTB;
    const int dg = jg;
    for (int h = 0; h < 2; h++) {
        float c2[2][8][4];
#pragma unroll
        for (int rt = 0; rt < 2; rt++)
#pragma unroll
            for (int nt = 0; nt < 8; nt++)
#pragma unroll
                for (int c = 0; c < 4; c++) c2[rt][nt][c] = 0.f;

        const uint32_t thiB = sb + AU_HI + toff + (uint32_t)(h*128 + dg*64) * 2;
        const uint32_t tloB = sb + AU_LO + toff + (uint32_t)(h*128 + dg*64) * 2;
#pragma unroll 2
        for (int ksl = 0; ksl < 8; ksl++) {
            uint32_t ak = (uint32_t)ksl * 32;           // P col bytes
            uint32_t jk = (uint32_t)ksl * 16 * USTB;    // U row (j) offset
            uint32_t ah0[4], ah1[4], al0[4], al1[4];
            ldsm4(ah0, phi + ak);
            ldsm4(ah1, phi + ak + 16u*HSTB);
            ldsm4(al0, plo + ak);
            ldsm4(al1, plo + ak + 16u*HSTB);
#pragma unroll
            for (int nt2 = 0; nt2 < 4; nt2++) {
                uint32_t dbo = jk + (uint32_t)(nt2*16) * 2;
                uint32_t bh[4], bl[4];
                ldsm4t(bh, thiB + dbo);
                mma16816(c2[0][2*nt2],   ah0, bh[0], bh[1]);
                mma16816(c2[0][2*nt2+1], ah0, bh[2], bh[3]);
                mma16816(c2[1][2*nt2],   ah1, bh[0], bh[1]);
                mma16816(c2[1][2*nt2+1], ah1, bh[2], bh[3]);
                mma16816(c2[0][2*nt2],   al0, bh[0], bh[1]);
                mma16816(c2[0][2*nt2+1], al0, bh[2], bh[3]);
                mma16816(c2[1][2*nt2],   al1, bh[0], bh[1]);
                mma16816(c2[1][2*nt2+1], al1, bh[2], bh[3]);
                ldsm4t(bl, tloB + dbo);
                mma16816(c2[0][2*nt2],   ah0, bl[0], bl[1]);
                mma16816(c2[0][2*nt2+1], ah0, bl[2], bl[3]);
                mma16816(c2[1][2*nt2],   ah1, bl[0], bl[1]);
                mma16816(c2[1][2*nt2+1], ah1, bl[2], bl[3]);
            }
        }
        // epilogue for this d-half: G chunks [H, C2Q, H*C2Q]
#pragma unroll
        for (int rt = 0; rt < 2; rt++)
#pragma unroll
            for (int hf = 0; hf < 2; hf++) {
                int r = rbase + rt*16 + hf*8 + (lane >> 2);
                float inv = invS[r];
                size_t rowo = (size_t)(b*T_ + tb + r);
#pragma unroll
                for (int nt = 0; nt < 8; nt++) {
                    int d = h*128 + dg*64 + nt*8 + (lane & 3)*2;
                    float2 hv = *(const float2*)(H + rowo*D_ + d);
                    float q0 = c2[rt][nt][2*hf]   * inv;
                    float q1 = c2[rt][nt][2*hf+1] * inv;
                    float* Gr = G + rowo*(4*D_) + d;
                    *(float2*)(Gr)          = hv;
                    *(float2*)(Gr + D_)     = make_float2(q0, q1);
                    *(float2*)(Gr + 2*D_)   = make_float2(hv.x*q0, hv.y*q1);
                }
            }
    }
}

// ---------------------------------------------------------------------------
// K2a: per batch softmax over t of L -> g_Wt
__global__ void __launch_bounds__(1024)
bidaf_tsm()
{
    const int b = blockIdx.x, tid = threadIdx.x;
    __shared__ float red[32];
    const int lane = tid & 31, wid = tid >> 5;
    float l = g_L[b*T_ + tid];
    float m = l;
#pragma unroll
    for (int o = 16; o; o >>= 1) m = fmaxf(m, __shfl_xor_sync(0xffffffffu, m, o));
    if (lane == 0) red[wid] = m;
    __syncthreads();
    if (wid == 0) {
        float v = red[lane];
#pragma unroll
        for (int o = 16; o; o >>= 1) v = fmaxf(v, __shfl_xor_sync(0xffffffffu, v, o));
        if (lane == 0) red[0] = v;
    }
    __syncthreads();
    m = red[0];
    float e = __expf(l - m);
    float s = e;
#pragma unroll
    for (int o = 16; o; o >>= 1) s += __shfl_xor_sync(0xffffffffu, s, o);
    __syncthreads();
    if (lane == 0) red[wid] = s;
    __syncthreads();
    if (wid == 0) {
        float v = red[lane];
#pragma unroll
        for (int o = 16; o; o >>= 1) v += __shfl_xor_sync(0xffffffffu, v, o);
        if (lane == 0) red[0] = v;
    }
    __syncthreads();
    g_Wt[b*T_ + tid] = e / red[0];
}

// K2b: split-K partial Q2C
__global__ void __launch_bounds__(256)
bidaf_q2cp(const float* __restrict__ H)
{
    const int seg = blockIdx.x, b = blockIdx.y, d = threadIdx.x;
    const int t0 = seg * 128;
    const float* Hp = H + ((size_t)(b*T_ + t0))*D_ + d;
    const float* wp = g_Wt + b*T_ + t0;
    float acc = 0.f;
#pragma unroll 4
    for (int tt = 0; tt < 128; tt++)
        acc = fmaf(__ldg(wp + tt), Hp[(size_t)tt * D_], acc);
    g_Q2Cp[((size_t)(b*8 + seg))*D_ + d] = acc;
}

// K2c: reduce partials
__global__ void __launch_bounds__(256)
bidaf_q2cr()
{
    const int b = blockIdx.x, d = threadIdx.x;
    float s = 0.f;
#pragma unroll
    for (int seg = 0; seg < 8; seg++)
        s += g_Q2Cp[((size_t)(b*8 + seg))*D_ + d];
    g_Q2C[b*D_ + d] = s;
}

// K3: G chunk 3 = H * Q2C
__global__ void __launch_bounds__(256)
bidaf_g3(const float* __restrict__ H, float* __restrict__ G)
{
    int idx = blockIdx.x * 256 + threadIdx.x;
    int d4 = idx & 63;
    int t  = (idx >> 6) & (T_-1);
    int b  = idx >> 16;
    float4 h = ((const float4*)H)[idx];
    float4 q = ((const float4*)g_Q2C)[b*(D_/4) + d4];
    float4 o = make_float4(h.x*q.x, h.y*q.y, h.z*q.z, h.w*q.w);
    ((float4*)G)[((size_t)(b*T_ + t))*(4*D_/4) + 3*(D_/4) + d4] = o;
}

// ---------------------------------------------------------------------------
extern "C" void kernel_launch(void* const* d_in, const int* in_sizes, int n_in,
                              void* d_out, int out_size)
{
    const float* H   = (const float*)d_in[0];
    const float* U   = (const float*)d_in[1];
    const float* wh  = (const float*)d_in[2];
    const float* wu  = (const float*)d_in[3];
    const float* whu = (const float*)d_in[4];
    float* G = (float*)d_out;

    cudaFuncSetAttribute(bidaf_main, cudaFuncAttributeMaxDynamicSharedMemorySize, SMEM_TOTAL);

    dim3 g1(T_/TT, B_);
    bidaf_main<<<g1, 256, SMEM_TOTAL>>>(H, U, wh, wu, whu, G);
    bidaf_tsm<<<B_, 1024>>>();
    bidaf_q2cp<<<dim3(8, B_), 256>>>(H);
    bidaf_q2cr<<<B_, 256>>>();
    bidaf_g3<<<(B_*T_*D_/4)/256, 256>>>(H, G);
}

// round 12
// speedup vs baseline: 2.4163x; 1.0841x over previous
#include <cuda_runtime.h>
#include <cuda_bf16.h>
#include <stdint.h>

#define B_  64
#define T_  1024
#define J_  128
#define D_  256
#define TT  128

// strides (bf16 elems / bytes)
#define USTB 528     // U row stride bytes (264 bf16): 132 words ≡ 4 mod 32 -> conflict-free ldmatrix
#define HSTB 272     // H/P row stride bytes (136 bf16): 68 words ≡ 4 mod 32

// smem byte offsets
#define SM_SH   0
#define SM_SU   512
#define SM_INV  1024
#define SM_RM   1536
#define SM_RS   3584
#define SM_L    5632                    // L[128] f32 (ends 6144 < 8192)
#define AU_HI   8192
#define AU_LO   (AU_HI + J_*USTB)       // +67584
#define AH_HI   (AU_LO + J_*USTB)
#define AH_LO   (AH_HI + TT*HSTB)       // +34816
#define SMEM_TOTAL (AH_LO + TT*HSTB)    // 213504 B
#define AP_HI   AH_HI                   // P overlays H after GEMM1
#define AP_LO   AH_LO
#define SM_VR   AU_HI                   // V-partial cross-warp reduce [8][256] f32 (U dead by then)
#define SM_VS   (AU_HI + 8192)          // s_c partials [8] f32

__device__ __align__(16) float g_Vp[B_*8*D_];   // per-tile V_c
__device__ __align__(16) float g_Ms[B_*8*2];    // per-tile {M_c, s_c}

// ---------------- helpers ----------------
__device__ __forceinline__ uint32_t smem_u32(const void* p) {
    uint32_t a;
    asm("{ .reg .u64 t; cvta.to.shared.u64 t, %1; cvt.u32.u64 %0, t; }" : "=r"(a) : "l"(p));
    return a;
}
__device__ __forceinline__ void ldsm4(uint32_t* r, uint32_t addr) {
    asm volatile("ldmatrix.sync.aligned.m8n8.x4.shared.b16 {%0,%1,%2,%3}, [%4];"
        : "=r"(r[0]), "=r"(r[1]), "=r"(r[2]), "=r"(r[3]) : "r"(addr));
}
__device__ __forceinline__ void ldsm4t(uint32_t* r, uint32_t addr) {
    asm volatile("ldmatrix.sync.aligned.m8n8.x4.trans.shared.b16 {%0,%1,%2,%3}, [%4];"
        : "=r"(r[0]), "=r"(r[1]), "=r"(r[2]), "=r"(r[3]) : "r"(addr));
}
__device__ __forceinline__ void mma16816(float* c, const uint32_t* a, uint32_t b0, uint32_t b1) {
    asm volatile("mma.sync.aligned.m16n8k16.row.col.f32.bf16.bf16.f32 "
        "{%0,%1,%2,%3}, {%4,%5,%6,%7}, {%8,%9}, {%0,%1,%2,%3};"
        : "+f"(c[0]), "+f"(c[1]), "+f"(c[2]), "+f"(c[3])
        : "r"(a[0]), "r"(a[1]), "r"(a[2]), "r"(a[3]), "r"(b0), "r"(b1));
}
static __device__ __forceinline__ uint32_t pk(float a, float b) {
    return (uint32_t)__bfloat16_as_ushort(__float2bfloat16(a))
         | ((uint32_t)__bfloat16_as_ushort(__float2bfloat16(b)) << 16);
}
static __device__ __forceinline__ float rsd(float x) {
    return x - __bfloat162float(__float2bfloat16(x));
}

// ---------------------------------------------------------------------------
// K1: HMMA main kernel. 1 CTA per (b, 128-row t-tile). 8 warps.
// ---------------------------------------------------------------------------
__global__ void __launch_bounds__(256, 1)
bidaf_main(const float* __restrict__ H, const float* __restrict__ U,
           const float* __restrict__ w_h, const float* __restrict__ w_u,
           const float* __restrict__ w_hu, float* __restrict__ G)
{
    extern __shared__ char smem[];
    const uint32_t sb = smem_u32(smem);
    float* shS  = (float*)(smem + SM_SH);
    float* suS  = (float*)(smem + SM_SU);
    float* invS = (float*)(smem + SM_INV);
    float* redM = (float*)(smem + SM_RM);
    float* redS = (float*)(smem + SM_RS);
    float* Lsm  = (float*)(smem + SM_L);

    const int tid  = threadIdx.x;
    const int lane = tid & 31;
    const int warp = tid >> 5;
    const int rg   = warp & 3;
    const int jg   = warp >> 2;
    const int rbase = rg * 32;
    const int b    = blockIdx.y;
    const int tb   = blockIdx.x * TT;

    const int lr = lane & 7;
    const int g  = lane >> 3;
    const uint32_t aoff = (uint32_t)((((g & 1) << 3) + lr) * HSTB + ((g >> 1) << 4));
    const uint32_t boff = (uint32_t)((((g >> 1) << 3) + lr) * USTB + ((g & 1) << 4));
    const uint32_t toff = (uint32_t)((((g & 1) << 3) + lr) * USTB + ((g >> 1) << 4));

    // ---- stage U full-K (hi/lo) + su ----
    {
        const float4* wu4 = (const float4*)w_u;
        float4 wa = wu4[lane], wb = wu4[32 + lane];
#pragma unroll
        for (int it = 0; it < 16; it++) {
            int j = warp + it * 8;
            const float4* Uj = (const float4*)(U + (size_t)(b * J_ + j) * D_);
            float4 v0 = Uj[lane], v1 = Uj[32 + lane];
            float s = v0.x*wa.x + v0.y*wa.y + v0.z*wa.z + v0.w*wa.w
                    + v1.x*wb.x + v1.y*wb.y + v1.z*wb.z + v1.w*wb.w;
#pragma unroll
            for (int o = 16; o; o >>= 1) s += __shfl_xor_sync(0xffffffffu, s, o);
            if (lane == 0) suS[j] = s;
            uint32_t ro = (uint32_t)j * USTB + (uint32_t)lane * 8;
            *(uint2*)(smem + AU_HI + ro)       = make_uint2(pk(v0.x,v0.y), pk(v0.z,v0.w));
            *(uint2*)(smem + AU_HI + ro + 256) = make_uint2(pk(v1.x,v1.y), pk(v1.z,v1.w));
            *(uint2*)(smem + AU_LO + ro)       = make_uint2(pk(rsd(v0.x),rsd(v0.y)), pk(rsd(v0.z),rsd(v0.w)));
            *(uint2*)(smem + AU_LO + ro + 256) = make_uint2(pk(rsd(v1.x),rsd(v1.y)), pk(rsd(v1.z),rsd(v1.w)));
        }
    }

    float acc[2][8][4];
#pragma unroll
    for (int rt = 0; rt < 2; rt++)
#pragma unroll
        for (int nt = 0; nt < 8; nt++)
#pragma unroll
            for (int c = 0; c < 4; c++) acc[rt][nt][c] = 0.f;

    // ---- GEMM1 over two H k-chunks ----
    for (int kc = 0; kc < 2; kc++) {
        if (kc == 1) __syncthreads();
        {
            const float4* wh4  = (const float4*)w_h;
            const float4* whu4 = (const float4*)w_hu;
            float4 wv = wh4[kc*32 + lane];
            float4 mv = whu4[kc*32 + lane];
#pragma unroll
            for (int it = 0; it < 16; it++) {
                int row = warp + it * 8;
                float4 v = ((const float4*)(H + (size_t)(b*T_ + tb + row) * D_ + kc*128))[lane];
                float s = v.x*wv.x + v.y*wv.y + v.z*wv.z + v.w*wv.w;
#pragma unroll
                for (int o = 16; o; o >>= 1) s += __shfl_xor_sync(0xffffffffu, s, o);
                if (lane == 0) { if (kc == 0) shS[row] = s; else shS[row] += s; }
                float x0 = v.x*mv.x, x1 = v.y*mv.y, x2 = v.z*mv.z, x3 = v.w*mv.w;
                uint32_t ro = (uint32_t)row * HSTB + (uint32_t)lane * 8;
                *(uint2*)(smem + AH_HI + ro) = make_uint2(pk(x0,x1), pk(x2,x3));
                *(uint2*)(smem + AH_LO + ro) = make_uint2(pk(rsd(x0),rsd(x1)), pk(rsd(x2),rsd(x3)));
            }
        }
        __syncthreads();

        const uint32_t ahi = sb + AH_HI + aoff + (uint32_t)rbase * HSTB;
        const uint32_t alo = sb + AH_LO + aoff + (uint32_t)rbase * HSTB;
        const uint32_t bhiB = sb + AU_HI + boff + (uint32_t)(kc * 256);
        const uint32_t bloB = sb + AU_LO + boff + (uint32_t)(kc * 256);
#pragma unroll 2
        for (int ksl = 0; ksl < 8; ksl++) {
            uint32_t ak = (uint32_t)ksl * 32;
            uint32_t ah0[4], ah1[4], al0[4], al1[4];
            ldsm4(ah0, ahi + ak);
            ldsm4(ah1, ahi + ak + 16u*HSTB);
            ldsm4(al0, alo + ak);
            ldsm4(al1, alo + ak + 16u*HSTB);
#pragma unroll
            for (int nt2 = 0; nt2 < 4; nt2++) {
                uint32_t jb = (uint32_t)(jg*64 + nt2*16) * USTB + ak;
                uint32_t bh[4], bl[4];
                ldsm4(bh, bhiB + jb);
                mma16816(acc[0][2*nt2],   ah0, bh[0], bh[1]);
                mma16816(acc[0][2*nt2+1], ah0, bh[2], bh[3]);
                mma16816(acc[1][2*nt2],   ah1, bh[0], bh[1]);
                mma16816(acc[1][2*nt2+1], ah1, bh[2], bh[3]);
                mma16816(acc[0][2*nt2],   al0, bh[0], bh[1]);
                mma16816(acc[0][2*nt2+1], al0, bh[2], bh[3]);
                mma16816(acc[1][2*nt2],   al1, bh[0], bh[1]);
                mma16816(acc[1][2*nt2+1], al1, bh[2], bh[3]);
                ldsm4(bl, bloB + jb);
                mma16816(acc[0][2*nt2],   ah0, bl[0], bl[1]);
                mma16816(acc[0][2*nt2+1], ah0, bl[2], bl[3]);
                mma16816(acc[1][2*nt2],   ah1, bl[0], bl[1]);
                mma16816(acc[1][2*nt2+1], ah1, bl[2], bl[3]);
            }
        }
    }

    // ---- softmax over j ----
    {
        const int q2 = (lane & 3) * 2;
        float su2[8][2];
#pragma unroll
        for (int nt = 0; nt < 8; nt++) {
            float2 s2 = *(const float2*)(suS + jg*64 + nt*8 + q2);
            su2[nt][0] = s2.x; su2[nt][1] = s2.y;
        }
        float mx[4];
#pragma unroll
        for (int rt = 0; rt < 2; rt++)
#pragma unroll
            for (int hf = 0; hf < 2; hf++) {
                float m = -1e30f;
#pragma unroll
                for (int nt = 0; nt < 8; nt++) {
                    float v0 = acc[rt][nt][2*hf]   + su2[nt][0];
                    float v1 = acc[rt][nt][2*hf+1] + su2[nt][1];
                    acc[rt][nt][2*hf] = v0; acc[rt][nt][2*hf+1] = v1;
                    m = fmaxf(m, fmaxf(v0, v1));
                }
                m = fmaxf(m, __shfl_xor_sync(0xffffffffu, m, 1));
                m = fmaxf(m, __shfl_xor_sync(0xffffffffu, m, 2));
                mx[2*rt+hf] = m;
            }
        const int rI = rbase + (lane >> 2);
        if ((lane & 3) == 0) {
#pragma unroll
            for (int rt = 0; rt < 2; rt++)
#pragma unroll
                for (int hf = 0; hf < 2; hf++)
                    redM[jg*128 + rI + rt*16 + hf*8] = mx[2*rt+hf];
        }
        __syncthreads();
        float mf[4], sm[4];
#pragma unroll
        for (int rt = 0; rt < 2; rt++)
#pragma unroll
            for (int hf = 0; hf < 2; hf++) {
                int r = rI + rt*16 + hf*8;
                float m = fmaxf(redM[r], redM[128 + r]);
                mf[2*rt+hf] = m;
                float s = 0.f;
#pragma unroll
                for (int nt = 0; nt < 8; nt++) {
                    float e0 = __expf(acc[rt][nt][2*hf]   - m);
                    float e1 = __expf(acc[rt][nt][2*hf+1] - m);
                    acc[rt][nt][2*hf] = e0; acc[rt][nt][2*hf+1] = e1;
                    s += e0 + e1;
                }
                s += __shfl_xor_sync(0xffffffffu, s, 1);
                s += __shfl_xor_sync(0xffffffffu, s, 2);
                sm[2*rt+hf] = s;
            }
        if ((lane & 3) == 0) {
#pragma unroll
            for (int k = 0; k < 4; k++)
                redS[jg*128 + rI + (k>>1)*16 + (k&1)*8] = sm[k];
        }
        __syncthreads();
#pragma unroll
        for (int rt = 0; rt < 2; rt++)
#pragma unroll
            for (int hf = 0; hf < 2; hf++) {
                int r = rI + rt*16 + hf*8;
                if (jg == 0 && (lane & 3) == 0) {
                    float tot = redS[r] + redS[128 + r];
                    invS[r] = 1.0f / tot;
                    Lsm[r] = shS[r] + mf[2*rt+hf];
                }
#pragma unroll
                for (int nt = 0; nt < 8; nt++) {
                    float e0 = acc[rt][nt][2*hf], e1 = acc[rt][nt][2*hf+1];
                    uint32_t o = (uint32_t)r * HSTB + (uint32_t)(jg*64 + nt*8 + q2) * 2;
                    *(uint32_t*)(smem + AP_HI + o) = pk(e0, e1);
                    *(uint32_t*)(smem + AP_LO + o) = pk(rsd(e0), rsd(e1));
                }
            }
    }
    __syncthreads();

    // ---- GEMM2 (two d-halves) + epilogue ----
    const uint32_t phi = sb + AP_HI + aoff + (uint32_t)rbase * HSTB;
    const uint32_t plo = sb + AP_LO + aoff + (uint32_t)rbase * HSTB;
    const int dg = jg;
    for (int h = 0; h < 2; h++) {
        float c2[2][8][4];
#pragma unroll
        for (int rt = 0; rt < 2; rt++)
#pragma unroll
            for (int nt = 0; nt < 8; nt++)
#pragma unroll
                for (int c = 0; c < 4; c++) c2[rt][nt][c] = 0.f;

        const uint32_t thiB = sb + AU_HI + toff + (uint32_t)(h*128 + dg*64) * 2;
        const uint32_t tloB = sb + AU_LO + toff + (uint32_t)(h*128 + dg*64) * 2;
#pragma unroll 2
        for (int ksl = 0; ksl < 8; ksl++) {
            uint32_t ak = (uint32_t)ksl * 32;
            uint32_t jk = (uint32_t)ksl * 16 * USTB;
            uint32_t ah0[4], ah1[4], al0[4], al1[4];
            ldsm4(ah0, phi + ak);
            ldsm4(ah1, phi + ak + 16u*HSTB);
            ldsm4(al0, plo + ak);
            ldsm4(al1, plo + ak + 16u*HSTB);
#pragma unroll
            for (int nt2 = 0; nt2 < 4; nt2++) {
                uint32_t dbo = jk + (uint32_t)(nt2*16) * 2;
                uint32_t bh[4], bl[4];
                ldsm4t(bh, thiB + dbo);
                mma16816(c2[0][2*nt2],   ah0, bh[0], bh[1]);
                mma16816(c2[0][2*nt2+1], ah0, bh[2], bh[3]);
                mma16816(c2[1][2*nt2],   ah1, bh[0], bh[1]);
                mma16816(c2[1][2*nt2+1], ah1, bh[2], bh[3]);
                mma16816(c2[0][2*nt2],   al0, bh[0], bh[1]);
                mma16816(c2[0][2*nt2+1], al0, bh[2], bh[3]);
                mma16816(c2[1][2*nt2],   al1, bh[0], bh[1]);
                mma16816(c2[1][2*nt2+1], al1, bh[2], bh[3]);
                ldsm4t(bl, tloB + dbo);
                mma16816(c2[0][2*nt2],   ah0, bl[0], bl[1]);
                mma16816(c2[0][2*nt2+1], ah0, bl[2], bl[3]);
                mma16816(c2[1][2*nt2],   ah1, bl[0], bl[1]);
                mma16816(c2[1][2*nt2+1], ah1, bl[2], bl[3]);
            }
        }
#pragma unroll
        for (int rt = 0; rt < 2; rt++)
#pragma unroll
            for (int hf = 0; hf < 2; hf++) {
                int r = rbase + rt*16 + hf*8 + (lane >> 2);
                float inv = invS[r];
                size_t rowo = (size_t)(b*T_ + tb + r);
#pragma unroll
                for (int nt = 0; nt < 8; nt++) {
                    int d = h*128 + dg*64 + nt*8 + (lane & 3)*2;
                    float2 hv = *(const float2*)(H + rowo*D_ + d);
                    float q0 = c2[rt][nt][2*hf]   * inv;
                    float q1 = c2[rt][nt][2*hf+1] * inv;
                    float* Gr = G + rowo*(4*D_) + d;
                    *(float2*)(Gr)          = hv;
                    *(float2*)(Gr + D_)     = make_float2(q0, q1);
                    *(float2*)(Gr + 2*D_)   = make_float2(hv.x*q0, hv.y*q1);
                }
            }
    }

    // ---- V-partial phase: M_c, s_c, V_c[d] for this t-tile ----
    __syncthreads();   // all ldmatrix reads of U done; Lsm complete; AU area reusable
    {
        // per-warp redundant tile max
        float lm = fmaxf(fmaxf(Lsm[lane], Lsm[lane+32]), fmaxf(Lsm[lane+64], Lsm[lane+96]));
#pragma unroll
        for (int o = 16; o; o >>= 1) lm = fmaxf(lm, __shfl_xor_sync(0xffffffffu, lm, o));

        float4 a0 = make_float4(0.f,0.f,0.f,0.f), a1 = make_float4(0.f,0.f,0.f,0.f);
        float sc = 0.f;
#pragma unroll 4
        for (int rr = 0; rr < 16; rr++) {
            int r = warp*16 + rr;
            float w = __expf(Lsm[r] - lm);
            const float4* Hr = (const float4*)(H + (size_t)(b*T_ + tb + r) * D_);
            float4 h0 = Hr[lane], h1 = Hr[lane + 32];
            a0.x = fmaf(w, h0.x, a0.x); a0.y = fmaf(w, h0.y, a0.y);
            a0.z = fmaf(w, h0.z, a0.z); a0.w = fmaf(w, h0.w, a0.w);
            a1.x = fmaf(w, h1.x, a1.x); a1.y = fmaf(w, h1.y, a1.y);
            a1.z = fmaf(w, h1.z, a1.z); a1.w = fmaf(w, h1.w, a1.w);
            sc += w;
        }
        float4* vred = (float4*)(smem + SM_VR + warp*1024);
        vred[lane]      = a0;
        vred[lane + 32] = a1;
        if (lane == 0) ((float*)(smem + SM_VS))[warp] = sc;
        __syncthreads();
        const float* vr = (const float*)(smem + SM_VR);
        float v = 0.f;
#pragma unroll
        for (int w = 0; w < 8; w++) v += vr[w*256 + tid];
        g_Vp[((size_t)(b*8 + blockIdx.x))*D_ + tid] = v;
        if (tid == 0) {
            const float* vs = (const float*)(smem + SM_VS);
            float st = 0.f;
#pragma unroll
            for (int w = 0; w < 8; w++) st += vs[w];
            g_Ms[(b*8 + blockIdx.x)*2]     = lm;
            g_Ms[(b*8 + blockIdx.x)*2 + 1] = st;
        }
    }
}

// ---------------------------------------------------------------------------
// K2: finalize Q2C per batch (redundant per CTA, trivial) + write G chunk 3.
// grid (T/16, B), 256 thr. Each CTA: 16 rows x full D.
// ---------------------------------------------------------------------------
__global__ void __launch_bounds__(256)
bidaf_g3f(const float* __restrict__ H, float* __restrict__ G)
{
    __shared__ __align__(16) float q2c[D_];
    const int b = blockIdx.y, tid = threadIdx.x;

    float m = -1e30f;
#pragma unroll
    for (int c = 0; c < 8; c++) m = fmaxf(m, g_Ms[(b*8 + c)*2]);
    float ssum = 0.f, v = 0.f;
#pragma unroll
    for (int c = 0; c < 8; c++) {
        float f = __expf(g_Ms[(b*8 + c)*2] - m);
        ssum = fmaf(f, g_Ms[(b*8 + c)*2 + 1], ssum);
        v    = fmaf(f, g_Vp[((size_t)(b*8 + c))*D_ + tid], v);
    }
    q2c[tid] = v / ssum;
    __syncthreads();

    const int tb = blockIdx.x * 16;
#pragma unroll
    for (int it = 0; it < 4; it++) {
        int idx = it*256 + tid;
        int row = idx >> 6, d4 = idx & 63;
        size_t rowo = (size_t)(b*T_ + tb + row);
        float4 h = ((const float4*)(H + rowo*D_))[d4];
        float4 q = ((const float4*)q2c)[d4];
        ((float4*)(G + rowo*(4*D_) + 3*D_))[d4] =
            make_float4(h.x*q.x, h.y*q.y, h.z*q.z, h.w*q.w);
    }
}

// ---------------------------------------------------------------------------
extern "C" void kernel_launch(void* const* d_in, const int* in_sizes, int n_in,
                              void* d_out, int out_size)
{
    const float* H   = (const float*)d_in[0];
    const float* U   = (const float*)d_in[1];
    const float* wh  = (const float*)d_in[2];
    const float* wu  = (const float*)d_in[3];
    const float* whu = (const float*)d_in[4];
    float* G = (float*)d_out;

    cudaFuncSetAttribute(bidaf_main, cudaFuncAttributeMaxDynamicSharedMemorySize, SMEM_TOTAL);

    dim3 g1(T_/TT, B_);
    bidaf_main<<<g1, 256, SMEM_TOTAL>>>(H, U, wh, wu, whu, G);
    bidaf_g3f<<<dim3(T_/16, B_), 256>>>(H, G);
}

// round 14
// speedup vs baseline: 2.4715x; 1.0229x over previous
#include <cuda_runtime.h>
#include <cuda_bf16.h>
#include <stdint.h>

#define B_  64
#define T_  1024
#define J_  128
#define D_  256
#define TT  128
#define NWARP 16

// strides (bytes)
#define USTB 528     // U row stride: 132 words ≡ 4 mod 32 -> conflict-free ldmatrix
#define HSTB 272     // H/P row stride: 68 words ≡ 4 mod 32

// smem byte offsets
#define SM_SH   0
#define SM_SU   512
#define SM_INV  1024
#define SM_RM   1536                    // [4][128] f32 = 2048
#define SM_RS   3584                    // [4][128] f32 = 2048
#define SM_L    5632                    // L[128] f32 (ends 6144 < 8192)
#define AU_HI   8192
#define AU_LO   (AU_HI + J_*USTB)       // +67584
#define AH_HI   (AU_LO + J_*USTB)
#define AH_LO   (AH_HI + TT*HSTB)       // +34816
#define SMEM_TOTAL (AH_LO + TT*HSTB)    // 213504 B
#define AP_HI   AH_HI                   // P overlays H after GEMM1
#define AP_LO   AH_LO
#define SM_VR   AU_HI                   // V reduce [16][256] f32 = 16384 (U dead)
#define SM_VS   (AU_HI + 16384)         // s_c partials [16] f32
#define SM_Q2C  (AU_HI + 16448)         // q2c[256] f32 (finisher)

__device__ __align__(16) float g_Vp[B_*8*D_];   // per-tile V_c
__device__ __align__(16) float g_Ms[B_*8*2];    // per-tile {M_c, s_c}
__device__ unsigned g_cnt[B_];                  // finisher counters (self-resetting)

// ---------------- helpers ----------------
__device__ __forceinline__ uint32_t smem_u32(const void* p) {
    uint32_t a;
    asm("{ .reg .u64 t; cvta.to.shared.u64 t, %1; cvt.u32.u64 %0, t; }" : "=r"(a) : "l"(p));
    return a;
}
__device__ __forceinline__ void ldsm4(uint32_t* r, uint32_t addr) {
    asm volatile("ldmatrix.sync.aligned.m8n8.x4.shared.b16 {%0,%1,%2,%3}, [%4];"
        : "=r"(r[0]), "=r"(r[1]), "=r"(r[2]), "=r"(r[3]) : "r"(addr));
}
__device__ __forceinline__ void ldsm4t(uint32_t* r, uint32_t addr) {
    asm volatile("ldmatrix.sync.aligned.m8n8.x4.trans.shared.b16 {%0,%1,%2,%3}, [%4];"
        : "=r"(r[0]), "=r"(r[1]), "=r"(r[2]), "=r"(r[3]) : "r"(addr));
}
__device__ __forceinline__ void mma16816(float* c, const uint32_t* a, uint32_t b0, uint32_t b1) {
    asm volatile("mma.sync.aligned.m16n8k16.row.col.f32.bf16.bf16.f32 "
        "{%0,%1,%2,%3}, {%4,%5,%6,%7}, {%8,%9}, {%0,%1,%2,%3};"
        : "+f"(c[0]), "+f"(c[1]), "+f"(c[2]), "+f"(c[3])
        : "r"(a[0]), "r"(a[1]), "r"(a[2]), "r"(a[3]), "r"(b0), "r"(b1));
}
static __device__ __forceinline__ uint32_t pk(float a, float b) {
    return (uint32_t)__bfloat16_as_ushort(__float2bfloat16(a))
         | ((uint32_t)__bfloat16_as_ushort(__float2bfloat16(b)) << 16);
}
static __device__ __forceinline__ float rsd(float x) {
    return x - __bfloat162float(__float2bfloat16(x));
}

// ---------------------------------------------------------------------------
// Single fused kernel. 1 CTA per (b, 128-row t-tile). 16 warps.
// ---------------------------------------------------------------------------
__global__ void __launch_bounds__(512, 1)
bidaf_main(const float* __restrict__ H, const float* __restrict__ U,
           const float* __restrict__ w_h, const float* __restrict__ w_u,
           const float* __restrict__ w_hu, float* __restrict__ G)
{
    extern __shared__ char smem[];
    const uint32_t sb = smem_u32(smem);
    float* shS  = (float*)(smem + SM_SH);
    float* suS  = (float*)(smem + SM_SU);
    float* invS = (float*)(smem + SM_INV);
    float* redM = (float*)(smem + SM_RM);
    float* redS = (float*)(smem + SM_RS);
    float* Lsm  = (float*)(smem + SM_L);
    __shared__ unsigned finOld;

    const int tid  = threadIdx.x;
    const int lane = tid & 31;
    const int warp = tid >> 5;
    const int rg   = warp & 3;
    const int jg   = warp >> 2;       // 0..3 (also dg in GEMM2)
    const int rbase = rg * 32;
    const int b    = blockIdx.y;
    const int tb   = blockIdx.x * TT;

    const int lr = lane & 7;
    const int g  = lane >> 3;
    const uint32_t aoff = (uint32_t)((((g & 1) << 3) + lr) * HSTB + ((g >> 1) << 4));
    const uint32_t boff = (uint32_t)((((g >> 1) << 3) + lr) * USTB + ((g & 1) << 4));
    const uint32_t toff = (uint32_t)((((g & 1) << 3) + lr) * USTB + ((g >> 1) << 4));

    // ---- stage U full-K (hi/lo) + su ----
    {
        const float4* wu4 = (const float4*)w_u;
        float4 wa = wu4[lane], wb = wu4[32 + lane];
#pragma unroll
        for (int it = 0; it < 8; it++) {
            int j = warp + it * NWARP;
            const float4* Uj = (const float4*)(U + (size_t)(b * J_ + j) * D_);
            float4 v0 = Uj[lane], v1 = Uj[32 + lane];
            float s = v0.x*wa.x + v0.y*wa.y + v0.z*wa.z + v0.w*wa.w
                    + v1.x*wb.x + v1.y*wb.y + v1.z*wb.z + v1.w*wb.w;
#pragma unroll
            for (int o = 16; o; o >>= 1) s += __shfl_xor_sync(0xffffffffu, s, o);
            if (lane == 0) suS[j] = s;
            uint32_t ro = (uint32_t)j * USTB + (uint32_t)lane * 8;
            *(uint2*)(smem + AU_HI + ro)       = make_uint2(pk(v0.x,v0.y), pk(v0.z,v0.w));
            *(uint2*)(smem + AU_HI + ro + 256) = make_uint2(pk(v1.x,v1.y), pk(v1.z,v1.w));
            *(uint2*)(smem + AU_LO + ro)       = make_uint2(pk(rsd(v0.x),rsd(v0.y)), pk(rsd(v0.z),rsd(v0.w)));
            *(uint2*)(smem + AU_LO + ro + 256) = make_uint2(pk(rsd(v1.x),rsd(v1.y)), pk(rsd(v1.z),rsd(v1.w)));
        }
    }

    float acc[2][4][4];
#pragma unroll
    for (int rt = 0; rt < 2; rt++)
#pragma unroll
        for (int nt = 0; nt < 4; nt++)
#pragma unroll
            for (int c = 0; c < 4; c++) acc[rt][nt][c] = 0.f;

    // ---- GEMM1 over two H k-chunks (32 j per warp) ----
    for (int kc = 0; kc < 2; kc++) {
        if (kc == 1) __syncthreads();
        {
            const float4* wh4  = (const float4*)w_h;
            const float4* whu4 = (const float4*)w_hu;
            float4 wv = wh4[kc*32 + lane];
            float4 mv = whu4[kc*32 + lane];
#pragma unroll
            for (int it = 0; it < 8; it++) {
                int row = warp + it * NWARP;
                float4 v = ((const float4*)(H + (size_t)(b*T_ + tb + row) * D_ + kc*128))[lane];
                float s = v.x*wv.x + v.y*wv.y + v.z*wv.z + v.w*wv.w;
#pragma unroll
                for (int o = 16; o; o >>= 1) s += __shfl_xor_sync(0xffffffffu, s, o);
                if (lane == 0) { if (kc == 0) shS[row] = s; else shS[row] += s; }
                float x0 = v.x*mv.x, x1 = v.y*mv.y, x2 = v.z*mv.z, x3 = v.w*mv.w;
                uint32_t ro = (uint32_t)row * HSTB + (uint32_t)lane * 8;
                *(uint2*)(smem + AH_HI + ro) = make_uint2(pk(x0,x1), pk(x2,x3));
                *(uint2*)(smem + AH_LO + ro) = make_uint2(pk(rsd(x0),rsd(x1)), pk(rsd(x2),rsd(x3)));
            }
        }
        __syncthreads();

        const uint32_t ahi = sb + AH_HI + aoff + (uint32_t)rbase * HSTB;
        const uint32_t alo = sb + AH_LO + aoff + (uint32_t)rbase * HSTB;
        const uint32_t bhiB = sb + AU_HI + boff + (uint32_t)(kc * 256);
        const uint32_t bloB = sb + AU_LO + boff + (uint32_t)(kc * 256);
#pragma unroll 2
        for (int ksl = 0; ksl < 8; ksl++) {
            uint32_t ak = (uint32_t)ksl * 32;
            uint32_t ah0[4], ah1[4], al0[4], al1[4];
            ldsm4(ah0, ahi + ak);
            ldsm4(ah1, ahi + ak + 16u*HSTB);
            ldsm4(al0, alo + ak);
            ldsm4(al1, alo + ak + 16u*HSTB);
#pragma unroll
            for (int nt2 = 0; nt2 < 2; nt2++) {
                uint32_t jb = (uint32_t)(jg*32 + nt2*16) * USTB + ak;
                uint32_t bh[4], bl[4];
                ldsm4(bh, bhiB + jb);
                mma16816(acc[0][2*nt2],   ah0, bh[0], bh[1]);
                mma16816(acc[0][2*nt2+1], ah0, bh[2], bh[3]);
                mma16816(acc[1][2*nt2],   ah1, bh[0], bh[1]);
                mma16816(acc[1][2*nt2+1], ah1, bh[2], bh[3]);
                mma16816(acc[0][2*nt2],   al0, bh[0], bh[1]);
                mma16816(acc[0][2*nt2+1], al0, bh[2], bh[3]);
                mma16816(acc[1][2*nt2],   al1, bh[0], bh[1]);
                mma16816(acc[1][2*nt2+1], al1, bh[2], bh[3]);
                ldsm4(bl, bloB + jb);
                mma16816(acc[0][2*nt2],   ah0, bl[0], bl[1]);
                mma16816(acc[0][2*nt2+1], ah0, bl[2], bl[3]);
                mma16816(acc[1][2*nt2],   ah1, bl[0], bl[1]);
                mma16816(acc[1][2*nt2+1], ah1, bl[2], bl[3]);
            }
        }
    }

    // ---- softmax over j (4-way cross-warp) ----
    {
        const int q2 = (lane & 3) * 2;
        float su2[4][2];
#pragma unroll
        for (int nt = 0; nt < 4; nt++) {
            float2 s2 = *(const float2*)(suS + jg*32 + nt*8 + q2);
            su2[nt][0] = s2.x; su2[nt][1] = s2.y;
        }
        float mx[4];
#pragma unroll
        for (int rt = 0; rt < 2; rt++)
#pragma unroll
            for (int hf = 0; hf < 2; hf++) {
                float m = -1e30f;
#pragma unroll
                for (int nt = 0; nt < 4; nt++) {
                    float v0 = acc[rt][nt][2*hf]   + su2[nt][0];
                    float v1 = acc[rt][nt][2*hf+1] + su2[nt][1];
                    acc[rt][nt][2*hf] = v0; acc[rt][nt][2*hf+1] = v1;
                    m = fmaxf(m, fmaxf(v0, v1));
                }
                m = fmaxf(m, __shfl_xor_sync(0xffffffffu, m, 1));
                m = fmaxf(m, __shfl_xor_sync(0xffffffffu, m, 2));
                mx[2*rt+hf] = m;
            }
        const int rI = rbase + (lane >> 2);
        if ((lane & 3) == 0) {
#pragma unroll
            for (int rt = 0; rt < 2; rt++)
#pragma unroll
                for (int hf = 0; hf < 2; hf++)
                    redM[jg*128 + rI + rt*16 + hf*8] = mx[2*rt+hf];
        }
        __syncthreads();
        float mf[4], sm[4];
#pragma unroll
        for (int rt = 0; rt < 2; rt++)
#pragma unroll
            for (int hf = 0; hf < 2; hf++) {
                int r = rI + rt*16 + hf*8;
                float m = fmaxf(fmaxf(redM[r], redM[128 + r]),
                                fmaxf(redM[256 + r], redM[384 + r]));
                mf[2*rt+hf] = m;
                float s = 0.f;
#pragma unroll
                for (int nt = 0; nt < 4; nt++) {
                    float e0 = __expf(acc[rt][nt][2*hf]   - m);
                    float e1 = __expf(acc[rt][nt][2*hf+1] - m);
                    acc[rt][nt][2*hf] = e0; acc[rt][nt][2*hf+1] = e1;
                    s += e0 + e1;
                }
                s += __shfl_xor_sync(0xffffffffu, s, 1);
                s += __shfl_xor_sync(0xffffffffu, s, 2);
                sm[2*rt+hf] = s;
            }
        if ((lane & 3) == 0) {
#pragma unroll
            for (int k = 0; k < 4; k++)
                redS[jg*128 + rI + (k>>1)*16 + (k&1)*8] = sm[k];
        }
        __syncthreads();
#pragma unroll
        for (int rt = 0; rt < 2; rt++)
#pragma unroll
            for (int hf = 0; hf < 2; hf++) {
                int r = rI + rt*16 + hf*8;
                if (jg == 0 && (lane & 3) == 0) {
                    float tot = redS[r] + redS[128 + r] + redS[256 + r] + redS[384 + r];
                    invS[r] = 1.0f / tot;
                    Lsm[r] = shS[r] + mf[2*rt+hf];
                }
#pragma unroll
                for (int nt = 0; nt < 4; nt++) {
                    float e0 = acc[rt][nt][2*hf], e1 = acc[rt][nt][2*hf+1];
                    uint32_t o = (uint32_t)r * HSTB + (uint32_t)(jg*32 + nt*8 + q2) * 2;
                    *(uint32_t*)(smem + AP_HI + o) = pk(e0, e1);
                    *(uint32_t*)(smem + AP_LO + o) = pk(rsd(e0), rsd(e1));
                }
            }
    }
    __syncthreads();

    // ---- GEMM2 (64 d per warp, no h loop) + epilogue ----
    {
        const uint32_t phi = sb + AP_HI + aoff + (uint32_t)rbase * HSTB;
        const uint32_t plo = sb + AP_LO + aoff + (uint32_t)rbase * HSTB;
        const int dg = jg;
        float c2[2][8][4];
#pragma unroll
        for (int rt = 0; rt < 2; rt++)
#pragma unroll
            for (int nt = 0; nt < 8; nt++)
#pragma unroll
                for (int c = 0; c < 4; c++) c2[rt][nt][c] = 0.f;

        const uint32_t thiB = sb + AU_HI + toff + (uint32_t)(dg*64) * 2;
        const uint32_t tloB = sb + AU_LO + toff + (uint32_t)(dg*64) * 2;
#pragma unroll 2
        for (int ksl = 0; ksl < 8; ksl++) {
            uint32_t ak = (uint32_t)ksl * 32;
            uint32_t jk = (uint32_t)ksl * 16 * USTB;
            uint32_t ah0[4], ah1[4], al0[4], al1[4];
            ldsm4(ah0, phi + ak);
            ldsm4(ah1, phi + ak + 16u*HSTB);
            ldsm4(al0, plo + ak);
            ldsm4(al1, plo + ak + 16u*HSTB);
#pragma unroll
            for (int nt2 = 0; nt2 < 4; nt2++) {
                uint32_t dbo = jk + (uint32_t)(nt2*16) * 2;
                uint32_t bh[4], bl[4];
                ldsm4t(bh, thiB + dbo);
                mma16816(c2[0][2*nt2],   ah0, bh[0], bh[1]);
                mma16816(c2[0][2*nt2+1], ah0, bh[2], bh[3]);
                mma16816(c2[1][2*nt2],   ah1, bh[0], bh[1]);
                mma16816(c2[1][2*nt2+1], ah1, bh[2], bh[3]);
                mma16816(c2[0][2*nt2],   al0, bh[0], bh[1]);
                mma16816(c2[0][2*nt2+1], al0, bh[2], bh[3]);
                mma16816(c2[1][2*nt2],   al1, bh[0], bh[1]);
                mma16816(c2[1][2*nt2+1], al1, bh[2], bh[3]);
                ldsm4t(bl, tloB + dbo);
                mma16816(c2[0][2*nt2],   ah0, bl[0], bl[1]);
                mma16816(c2[0][2*nt2+1], ah0, bl[2], bl[3]);
                mma16816(c2[1][2*nt2],   ah1, bl[0], bl[1]);
                mma16816(c2[1][2*nt2+1], ah1, bl[2], bl[3]);
            }
        }
#pragma unroll
        for (int rt = 0; rt < 2; rt++)
#pragma unroll
            for (int hf = 0; hf < 2; hf++) {
                int r = rbase + rt*16 + hf*8 + (lane >> 2);
                float inv = invS[r];
                size_t rowo = (size_t)(b*T_ + tb + r);
#pragma unroll
                for (int nt = 0; nt < 8; nt++) {
                    int d = dg*64 + nt*8 + (lane & 3)*2;
                    float2 hv = *(const float2*)(H + rowo*D_ + d);
                    float q0 = c2[rt][nt][2*hf]   * inv;
                    float q1 = c2[rt][nt][2*hf+1] * inv;
                    float* Gr = G + rowo*(4*D_) + d;
                    *(float2*)(Gr)          = hv;
                    *(float2*)(Gr + D_)     = make_float2(q0, q1);
                    *(float2*)(Gr + 2*D_)   = make_float2(hv.x*q0, hv.y*q1);
                }
            }
    }

    // ---- V-partial phase ----
    __syncthreads();   // U reads done; Lsm complete; AU area reusable
    {
        float lm = fmaxf(fmaxf(Lsm[lane], Lsm[lane+32]), fmaxf(Lsm[lane+64], Lsm[lane+96]));
#pragma unroll
        for (int o = 16; o; o >>= 1) lm = fmaxf(lm, __shfl_xor_sync(0xffffffffu, lm, o));

        float4 a0 = make_float4(0.f,0.f,0.f,0.f), a1 = make_float4(0.f,0.f,0.f,0.f);
        float sc = 0.f;
#pragma unroll
        for (int rr = 0; rr < 8; rr++) {
            int r = warp*8 + rr;
            float w = __expf(Lsm[r] - lm);
            const float4* Hr = (const float4*)(H + (size_t)(b*T_ + tb + r) * D_);
            float4 h0 = Hr[lane], h1 = Hr[lane + 32];
            a0.x = fmaf(w, h0.x, a0.x); a0.y = fmaf(w, h0.y, a0.y);
            a0.z = fmaf(w, h0.z, a0.z); a0.w = fmaf(w, h0.w, a0.w);
            a1.x = fmaf(w, h1.x, a1.x); a1.y = fmaf(w, h1.y, a1.y);
            a1.z = fmaf(w, h1.z, a1.z); a1.w = fmaf(w, h1.w, a1.w);
            sc += w;
        }
        float4* vred = (float4*)(smem + SM_VR + warp*1024);
        vred[lane]      = a0;
        vred[lane + 32] = a1;
        if (lane == 0) ((float*)(smem + SM_VS))[warp] = sc;
        __syncthreads();
        if (tid < D_) {
            const float* vr = (const float*)(smem + SM_VR);
            float v = 0.f;
#pragma unroll
            for (int w = 0; w < NWARP; w++) v += vr[w*256 + tid];
            g_Vp[((size_t)(b*8 + blockIdx.x))*D_ + tid] = v;
        }
        if (tid == 256) {
            const float* vs = (const float*)(smem + SM_VS);
            float st = 0.f;
#pragma unroll
            for (int w = 0; w < NWARP; w++) st += vs[w];
            g_Ms[(b*8 + blockIdx.x)*2]     = lm;
            g_Ms[(b*8 + blockIdx.x)*2 + 1] = st;
        }
    }

    // ---- finisher: last CTA of batch merges partials, writes G chunk 3 ----
    __threadfence();
    __syncthreads();
    if (tid == 0) finOld = atomicAdd(&g_cnt[b], 1u);
    __syncthreads();
    if (finOld == 7u) {
        float* q2cS = (float*)(smem + SM_Q2C);
        if (tid < D_) {
            float m = -1e30f;
#pragma unroll
            for (int c = 0; c < 8; c++) m = fmaxf(m, g_Ms[(b*8 + c)*2]);
            float ssum = 0.f, v = 0.f;
#pragma unroll
            for (int c = 0; c < 8; c++) {
                float f = __expf(g_Ms[(b*8 + c)*2] - m);
                ssum = fmaf(f, g_Ms[(b*8 + c)*2 + 1], ssum);
                v    = fmaf(f, g_Vp[((size_t)(b*8 + c))*D_ + tid], v);
            }
            q2cS[tid] = v / ssum;
        }
        if (tid == 0) g_cnt[b] = 0u;     // reset for next replay
        __syncthreads();
#pragma unroll 4
        for (int it = 0; it < (T_*D_/4)/512; it++) {
            int idx = it*512 + tid;
            int row = idx >> 6, d4 = idx & 63;
            size_t rowo = (size_t)(b*T_ + row);
            float4 h = ((const float4*)(H + rowo*D_))[d4];
            float4 q = ((const float4*)q2cS)[d4];
            ((float4*)(G + rowo*(4*D_) + 3*D_))[d4] =
                make_float4(h.x*q.x, h.y*q.y, h.z*q.z, h.w*q.w);
        }
    }
}

// ---------------------------------------------------------------------------
extern "C" void kernel_launch(void* const* d_in, const int* in_sizes, int n_in,
                              void* d_out, int out_size)
{
    const float* H   = (const float*)d_in[0];
    const float* U   = (const float*)d_in[1];
    const float* wh  = (const float*)d_in[2];
    const float* wu  = (const float*)d_in[3];
    const float* whu = (const float*)d_in[4];
    float* G = (float*)d_out;

    cudaFuncSetAttribute(bidaf_main, cudaFuncAttributeMaxDynamicSharedMemorySize, SMEM_TOTAL);

    dim3 g1(T_/TT, B_);
    bidaf_main<<<g1, 512, SMEM_TOTAL>>>(H, U, wh, wu, whu, G);
}